// round 15
// baseline (speedup 1.0000x reference)
#include <cuda_runtime.h>
#include <cstdint>

// nODE: 50 Euler steps x <- x + DT*(x*gamma + tanh(x @ W^T + b)), M=32768, N=K=512.
// Legacy mma.sync.m16n8k8.tf32 (tcgen05 unavailable: harness PTX target = compute_103).
// R15 = R10 champion (CTA 128x128, 8 warps 64x32, BK=32, ROWW=40 padded rows,
// k-permuted LDS.64 fragments, cp.async double buffer, bias-folded accumulators,
// tanh.approx epilogue) + outer-loop unroll-by-2 (specializes stage index, removes
// per-iter stage-select ALU) + interleaved A/B cp.async issue order.

constexpr int Mtot = 32768;
constexpr int Ntot = 512;
constexpr int Ktot = 512;
constexpr int BM = 128;
constexpr int BN = 128;
constexpr int BK = 32;
constexpr int NKT = Ktot / BK;          // 16 (even: unroll-2 safe)
constexpr int ROWW = 40;                // words per smem row: 32 data + 8 pad (160B)
constexpr int A_WORDS = BM * ROWW;      // 5120
constexpr int B_WORDS = BN * ROWW;      // 5120
constexpr int STAGE_WORDS = A_WORDS + B_WORDS;       // 10240 (40 KB)
constexpr int SMEM_BYTES = 2 * STAGE_WORDS * 4;      // 81920
constexpr int NSTEPS = 50;
constexpr float DTF = 1.0f / 50.0f;

// ping-pong scratch (allocation-free rule: __device__ globals)
__device__ float g_bufA[(size_t)Mtot * Ntot];
__device__ float g_bufB[(size_t)Mtot * Ntot];

__device__ __forceinline__ void cp_async16(uint32_t dst, const void* src) {
    asm volatile("cp.async.cg.shared.global [%0], [%1], 16;" :: "r"(dst), "l"(src) : "memory");
}
__device__ __forceinline__ uint32_t smem_u32(const void* p) {
    uint32_t a;
    asm("{ .reg .u64 t; cvta.to.shared.u64 t, %1; cvt.u32.u64 %0, t; }" : "=r"(a) : "l"(p));
    return a;
}
// single-instruction MUFU.TANH (~5e-4 abs err; DT-scaled contribution ~2e-4 total)
__device__ __forceinline__ float tanh_approx(float z) {
    float r;
    asm("tanh.approx.f32 %0, %1;" : "=f"(r) : "f"(z));
    return r;
}

__global__ __launch_bounds__(256, 2)
void node_step(const float* __restrict__ Xin, const float* __restrict__ W,
               const float* __restrict__ bias, const float* __restrict__ gamma,
               float* __restrict__ Xout)
{
    extern __shared__ __align__(16) float smem[];
    const uint32_t sbase = smem_u32(smem);

    const int tid  = threadIdx.x;
    const int wid  = tid >> 5;
    const int lane = tid & 31;
    const int g    = lane >> 2;          // 0..7 (fragment row group)
    const int tg   = lane & 3;           // 0..3 (fragment k group)
    const int wm   = wid >> 2;           // 0..1: warp row -> 64 M rows each
    const int wn   = wid & 3;            // 0..3: warp col -> 32 N cols each
    const int m0   = blockIdx.y * BM;
    const int n0   = blockIdx.x * BN;

    // Epilogue constants hoisted; bias folded into accumulator init (exact same math).
    float2 bv[4], gv[4];
    #pragma unroll
    for (int nt = 0; nt < 4; nt++) {
        int n = n0 + wn * 32 + nt * 8 + 2 * tg;
        bv[nt] = *reinterpret_cast<const float2*>(bias + n);
        gv[nt] = *reinterpret_cast<const float2*>(gamma + n);
    }

    float acc[4][4][4];
    #pragma unroll
    for (int mt = 0; mt < 4; mt++)
        #pragma unroll
        for (int nt = 0; nt < 4; nt++) {
            acc[mt][nt][0] = bv[nt].x;   // (row g,   col 2tg)
            acc[mt][nt][1] = bv[nt].y;   // (row g,   col 2tg+1)
            acc[mt][nt][2] = bv[nt].x;   // (row g+8, col 2tg)
            acc[mt][nt][3] = bv[nt].y;   // (row g+8, col 2tg+1)
        }

    // ---- hoisted loader state: 256 thr, 16B each -> 32 rows/pass, 4 passes per tile ----
    const int lr = tid >> 3;             // 0..31 row within pass
    const int lc = tid & 7;              // 0..7 16B chunk within 128B row
    const uint32_t s_off = (uint32_t)(lr * ROWW + lc * 4) * 4;
    const float* gAk = Xin + (size_t)(m0 + lr) * Ktot + lc * 4;  // bumped +BK per issue
    const float* gBk = W   + (size_t)(n0 + lr) * Ktot + lc * 4;

    auto issue_loads = [&](int s) {
        const uint32_t a_s = sbase + (uint32_t)(s * STAGE_WORDS) * 4 + s_off;
        const uint32_t b_s = a_s + (uint32_t)A_WORDS * 4;
        #pragma unroll
        for (int i = 0; i < 4; i++) {    // interleave the two L2 streams (A,B,A,B,...)
            cp_async16(a_s + (uint32_t)(i * 32 * ROWW) * 4, gAk + (size_t)(i * 32) * Ktot);
            cp_async16(b_s + (uint32_t)(i * 32 * ROWW) * 4, gBk + (size_t)(i * 32) * Ktot);
        }
        asm volatile("cp.async.commit_group;" ::: "memory");
        gAk += BK;
        gBk += BK;
    };

    issue_loads(0);

    const int cp0 = wid & 3;             // per-warp chunk phase (chunks commute)

    #pragma unroll 2
    for (int kt = 0; kt < NKT; kt++) {
        const int s = kt & 1;            // unroll-2 specializes s to a constant
        // issue into s^1 is safe: end-of-previous-iteration barrier guarantees all
        // warps finished reading stage s^1 (compute of iter kt-1).
        if (kt + 1 < NKT) {
            issue_loads(s ^ 1);
            asm volatile("cp.async.wait_group 1;" ::: "memory");  // own stage-s group done
        } else {
            asm volatile("cp.async.wait_group 0;" ::: "memory");
        }
        __syncthreads();   // ALL threads' stage-s cp.asyncs complete -> data visible

        const float* As = smem + s * STAGE_WORDS;
        const float* Bs = As + A_WORDS;
        const float* a_base = As + (wm * 64 + g) * ROWW + 2 * tg;
        const float* b_base = Bs + (wn * 32 + g) * ROWW + 2 * tg;

        #pragma unroll
        for (int ch = 0; ch < 4; ch++) {             // k chunks of 8, warp-staggered
            const int chp = (ch + cp0) & 3;
            // k-permutation: MMA k-slot tg <- orig col 2tg, slot tg+4 <- 2tg+1.
            // Valid because A and B use the same permutation of the k axis.
            uint32_t af[4][4];
            #pragma unroll
            for (int mt = 0; mt < 4; mt++) {
                const float* p = a_base + mt * 16 * ROWW + chp * 8;
                float2 p1 = *reinterpret_cast<const float2*>(p);
                float2 p2 = *reinterpret_cast<const float2*>(p + 8 * ROWW);
                af[mt][0] = __float_as_uint(p1.x);   // (g,    k=tg)
                af[mt][1] = __float_as_uint(p2.x);   // (g+8,  k=tg)
                af[mt][2] = __float_as_uint(p1.y);   // (g,    k=tg+4)
                af[mt][3] = __float_as_uint(p2.y);   // (g+8,  k=tg+4)
            }
            uint32_t bf[4][2];
            #pragma unroll
            for (int nt = 0; nt < 4; nt++) {
                float2 q = *reinterpret_cast<const float2*>(b_base + nt * 8 * ROWW + chp * 8);
                bf[nt][0] = __float_as_uint(q.x);
                bf[nt][1] = __float_as_uint(q.y);
            }
            #pragma unroll
            for (int mt = 0; mt < 4; mt++)
                #pragma unroll
                for (int nt = 0; nt < 4; nt++)
                    asm volatile(
                        "mma.sync.aligned.m16n8k8.row.col.f32.tf32.tf32.f32 "
                        "{%0,%1,%2,%3}, {%4,%5,%6,%7}, {%8,%9}, {%0,%1,%2,%3};"
                        : "+f"(acc[mt][nt][0]), "+f"(acc[mt][nt][1]),
                          "+f"(acc[mt][nt][2]), "+f"(acc[mt][nt][3])
                        : "r"(af[mt][0]), "r"(af[mt][1]),
                          "r"(af[mt][2]), "r"(af[mt][3]),
                          "r"(bf[nt][0]), "r"(bf[nt][1]));
        }
        __syncthreads();   // protect stage s overwrite at iter kt+1
    }

    // ---- fused epilogue: out = x + DT*(x*gamma + tanh(C)) (bias already in C) ----
    // D frag: d0,d1 at (row g,   cols 2tg,2tg+1); d2,d3 at (row g+8, same cols)
    #pragma unroll
    for (int mt = 0; mt < 4; mt++) {
        #pragma unroll
        for (int h = 0; h < 2; h++) {
            int m = m0 + wm * 64 + mt * 16 + g + h * 8;
            const float* xrow = Xin  + (size_t)m * Ntot;
            float*       orow = Xout + (size_t)m * Ntot;
            #pragma unroll
            for (int nt = 0; nt < 4; nt++) {
                int n = n0 + wn * 32 + nt * 8 + 2 * tg;
                float2 xv = *reinterpret_cast<const float2*>(xrow + n);
                float t0 = tanh_approx(acc[mt][nt][h * 2 + 0]);
                float t1 = tanh_approx(acc[mt][nt][h * 2 + 1]);
                float2 ov;
                ov.x = fmaf(DTF, fmaf(xv.x, gv[nt].x, t0), xv.x);
                ov.y = fmaf(DTF, fmaf(xv.y, gv[nt].y, t1), xv.y);
                *reinterpret_cast<float2*>(orow + n) = ov;
            }
        }
    }
}

extern "C" void kernel_launch(void* const* d_in, const int* in_sizes, int n_in,
                              void* d_out, int out_size)
{
    const float* x     = (const float*)d_in[0];
    const float* W     = (const float*)d_in[1];
    const float* b     = (const float*)d_in[2];
    const float* gamma = (const float*)d_in[3];
    float* out = (float*)d_out;

    float* bufA = nullptr;
    float* bufB = nullptr;
    cudaGetSymbolAddress((void**)&bufA, g_bufA);
    cudaGetSymbolAddress((void**)&bufB, g_bufB);

    cudaFuncSetAttribute(node_step, cudaFuncAttributeMaxDynamicSharedMemorySize, SMEM_BYTES);

    dim3 grid(Ntot / BN, Mtot / BM);   // (4, 256)
    dim3 block(256);

    for (int i = 0; i < NSTEPS; i++) {
        const float* src = (i == 0) ? x : ((i & 1) ? bufA : bufB);
        float* dst = (i == NSTEPS - 1) ? out : ((i & 1) ? bufB : bufA);
        node_step<<<grid, block, SMEM_BYTES>>>(src, W, b, gamma, dst);
    }
}

// round 16
// speedup vs baseline: 1.0166x; 1.0166x over previous
#include <cuda_runtime.h>
#include <cstdint>

// nODE: 50 Euler steps x <- x + DT*(x*gamma + tanh(x @ W^T + b)), M=32768, N=K=512.
// Legacy mma.sync.m16n8k8.tf32 (tcgen05 unavailable: harness PTX target = compute_103).
// FINAL (R10 champion, 5404us, rel_err 2.43e-4):
//   CTA 128x128, 8 warps of 64x32, BK=32, 160B padded smem rows (conflict-free),
//   k-permuted LDS.64 fragments, cp.async double buffer (wait -> barrier proven
//   ordering), hoisted loader addressing, warp-staggered chunk order,
//   bias folded into accumulator init, tanh.approx.f32 epilogue.
// Plateau: tensor and smem-crossbar floors coincide at this geometry (both ~50%
// active); tcgen05 (compute_103a) and larger warp tiles (regfile) are unavailable.

constexpr int Mtot = 32768;
constexpr int Ntot = 512;
constexpr int Ktot = 512;
constexpr int BM = 128;
constexpr int BN = 128;
constexpr int BK = 32;
constexpr int NKT = Ktot / BK;          // 16
constexpr int ROWW = 40;                // words per smem row: 32 data + 8 pad (160B)
constexpr int A_WORDS = BM * ROWW;      // 5120
constexpr int B_WORDS = BN * ROWW;      // 5120
constexpr int STAGE_WORDS = A_WORDS + B_WORDS;       // 10240 (40 KB)
constexpr int SMEM_BYTES = 2 * STAGE_WORDS * 4;      // 81920
constexpr int NSTEPS = 50;
constexpr float DTF = 1.0f / 50.0f;

// ping-pong scratch (allocation-free rule: __device__ globals)
__device__ float g_bufA[(size_t)Mtot * Ntot];
__device__ float g_bufB[(size_t)Mtot * Ntot];

__device__ __forceinline__ void cp_async16(uint32_t dst, const void* src) {
    asm volatile("cp.async.cg.shared.global [%0], [%1], 16;" :: "r"(dst), "l"(src) : "memory");
}
__device__ __forceinline__ uint32_t smem_u32(const void* p) {
    uint32_t a;
    asm("{ .reg .u64 t; cvta.to.shared.u64 t, %1; cvt.u32.u64 %0, t; }" : "=r"(a) : "l"(p));
    return a;
}
// single-instruction MUFU.TANH (~5e-4 abs err; DT-scaled contribution ~2e-4 total)
__device__ __forceinline__ float tanh_approx(float z) {
    float r;
    asm("tanh.approx.f32 %0, %1;" : "=f"(r) : "f"(z));
    return r;
}

__global__ __launch_bounds__(256, 2)
void node_step(const float* __restrict__ Xin, const float* __restrict__ W,
               const float* __restrict__ bias, const float* __restrict__ gamma,
               float* __restrict__ Xout)
{
    extern __shared__ __align__(16) float smem[];
    const uint32_t sbase = smem_u32(smem);

    const int tid  = threadIdx.x;
    const int wid  = tid >> 5;
    const int lane = tid & 31;
    const int g    = lane >> 2;          // 0..7 (fragment row group)
    const int tg   = lane & 3;           // 0..3 (fragment k group)
    const int wm   = wid >> 2;           // 0..1: warp row -> 64 M rows each
    const int wn   = wid & 3;            // 0..3: warp col -> 32 N cols each
    const int m0   = blockIdx.y * BM;
    const int n0   = blockIdx.x * BN;

    // Epilogue constants hoisted; bias folded into accumulator init (exact same math).
    float2 bv[4], gv[4];
    #pragma unroll
    for (int nt = 0; nt < 4; nt++) {
        int n = n0 + wn * 32 + nt * 8 + 2 * tg;
        bv[nt] = *reinterpret_cast<const float2*>(bias + n);
        gv[nt] = *reinterpret_cast<const float2*>(gamma + n);
    }

    float acc[4][4][4];
    #pragma unroll
    for (int mt = 0; mt < 4; mt++)
        #pragma unroll
        for (int nt = 0; nt < 4; nt++) {
            acc[mt][nt][0] = bv[nt].x;   // (row g,   col 2tg)
            acc[mt][nt][1] = bv[nt].y;   // (row g,   col 2tg+1)
            acc[mt][nt][2] = bv[nt].x;   // (row g+8, col 2tg)
            acc[mt][nt][3] = bv[nt].y;   // (row g+8, col 2tg+1)
        }

    // ---- hoisted loader state: 256 thr, 16B each -> 32 rows/pass, 4 passes per tile ----
    const int lr = tid >> 3;             // 0..31 row within pass
    const int lc = tid & 7;              // 0..7 16B chunk within 128B row
    const uint32_t s_off = (uint32_t)(lr * ROWW + lc * 4) * 4;
    const float* gAk = Xin + (size_t)(m0 + lr) * Ktot + lc * 4;  // bumped +BK per issue
    const float* gBk = W   + (size_t)(n0 + lr) * Ktot + lc * 4;

    auto issue_loads = [&](int s) {
        const uint32_t a_s = sbase + (uint32_t)(s * STAGE_WORDS) * 4 + s_off;
        const uint32_t b_s = a_s + (uint32_t)A_WORDS * 4;
        #pragma unroll
        for (int i = 0; i < 4; i++)      // A: 128 rows in 4 passes of 32
            cp_async16(a_s + (uint32_t)(i * 32 * ROWW) * 4, gAk + (size_t)(i * 32) * Ktot);
        #pragma unroll
        for (int i = 0; i < 4; i++)      // B: 128 rows
            cp_async16(b_s + (uint32_t)(i * 32 * ROWW) * 4, gBk + (size_t)(i * 32) * Ktot);
        asm volatile("cp.async.commit_group;" ::: "memory");
        gAk += BK;
        gBk += BK;
    };

    issue_loads(0);

    const int cp0 = wid & 3;             // per-warp chunk phase (chunks commute)

    for (int kt = 0; kt < NKT; kt++) {
        const int s = kt & 1;
        // issue into s^1 is safe: end-of-previous-iteration barrier guarantees all
        // warps finished reading stage s^1 (compute of iter kt-1).
        if (kt + 1 < NKT) {
            issue_loads(s ^ 1);
            asm volatile("cp.async.wait_group 1;" ::: "memory");  // own stage-s group done
        } else {
            asm volatile("cp.async.wait_group 0;" ::: "memory");
        }
        __syncthreads();   // ALL threads' stage-s cp.asyncs complete -> data visible

        const float* As = smem + s * STAGE_WORDS;
        const float* Bs = As + A_WORDS;
        const float* a_base = As + (wm * 64 + g) * ROWW + 2 * tg;
        const float* b_base = Bs + (wn * 32 + g) * ROWW + 2 * tg;

        #pragma unroll
        for (int ch = 0; ch < 4; ch++) {             // k chunks of 8, warp-staggered
            const int chp = (ch + cp0) & 3;
            // k-permutation: MMA k-slot tg <- orig col 2tg, slot tg+4 <- 2tg+1.
            // Valid because A and B use the same permutation of the k axis.
            uint32_t af[4][4];
            #pragma unroll
            for (int mt = 0; mt < 4; mt++) {
                const float* p = a_base + mt * 16 * ROWW + chp * 8;
                float2 p1 = *reinterpret_cast<const float2*>(p);
                float2 p2 = *reinterpret_cast<const float2*>(p + 8 * ROWW);
                af[mt][0] = __float_as_uint(p1.x);   // (g,    k=tg)
                af[mt][1] = __float_as_uint(p2.x);   // (g+8,  k=tg)
                af[mt][2] = __float_as_uint(p1.y);   // (g,    k=tg+4)
                af[mt][3] = __float_as_uint(p2.y);   // (g+8,  k=tg+4)
            }
            uint32_t bf[4][2];
            #pragma unroll
            for (int nt = 0; nt < 4; nt++) {
                float2 q = *reinterpret_cast<const float2*>(b_base + nt * 8 * ROWW + chp * 8);
                bf[nt][0] = __float_as_uint(q.x);
                bf[nt][1] = __float_as_uint(q.y);
            }
            #pragma unroll
            for (int mt = 0; mt < 4; mt++)
                #pragma unroll
                for (int nt = 0; nt < 4; nt++)
                    asm volatile(
                        "mma.sync.aligned.m16n8k8.row.col.f32.tf32.tf32.f32 "
                        "{%0,%1,%2,%3}, {%4,%5,%6,%7}, {%8,%9}, {%0,%1,%2,%3};"
                        : "+f"(acc[mt][nt][0]), "+f"(acc[mt][nt][1]),
                          "+f"(acc[mt][nt][2]), "+f"(acc[mt][nt][3])
                        : "r"(af[mt][0]), "r"(af[mt][1]),
                          "r"(af[mt][2]), "r"(af[mt][3]),
                          "r"(bf[nt][0]), "r"(bf[nt][1]));
        }
        __syncthreads();   // protect stage s overwrite at iter kt+1
    }

    // ---- fused epilogue: out = x + DT*(x*gamma + tanh(C)) (bias already in C) ----
    // D frag: d0,d1 at (row g,   cols 2tg,2tg+1); d2,d3 at (row g+8, same cols)
    #pragma unroll
    for (int mt = 0; mt < 4; mt++) {
        #pragma unroll
        for (int h = 0; h < 2; h++) {
            int m = m0 + wm * 64 + mt * 16 + g + h * 8;
            const float* xrow = Xin  + (size_t)m * Ntot;
            float*       orow = Xout + (size_t)m * Ntot;
            #pragma unroll
            for (int nt = 0; nt < 4; nt++) {
                int n = n0 + wn * 32 + nt * 8 + 2 * tg;
                float2 xv = *reinterpret_cast<const float2*>(xrow + n);
                float t0 = tanh_approx(acc[mt][nt][h * 2 + 0]);
                float t1 = tanh_approx(acc[mt][nt][h * 2 + 1]);
                float2 ov;
                ov.x = fmaf(DTF, fmaf(xv.x, gv[nt].x, t0), xv.x);
                ov.y = fmaf(DTF, fmaf(xv.y, gv[nt].y, t1), xv.y);
                *reinterpret_cast<float2*>(orow + n) = ov;
            }
        }
    }
}

extern "C" void kernel_launch(void* const* d_in, const int* in_sizes, int n_in,
                              void* d_out, int out_size)
{
    const float* x     = (const float*)d_in[0];
    const float* W     = (const float*)d_in[1];
    const float* b     = (const float*)d_in[2];
    const float* gamma = (const float*)d_in[3];
    float* out = (float*)d_out;

    float* bufA = nullptr;
    float* bufB = nullptr;
    cudaGetSymbolAddress((void**)&bufA, g_bufA);
    cudaGetSymbolAddress((void**)&bufB, g_bufB);

    cudaFuncSetAttribute(node_step, cudaFuncAttributeMaxDynamicSharedMemorySize, SMEM_BYTES);

    dim3 grid(Ntot / BN, Mtot / BM);   // (4, 256)
    dim3 block(256);

    for (int i = 0; i < NSTEPS; i++) {
        const float* src = (i == 0) ? x : ((i & 1) ? bufA : bufB);
        float* dst = (i == NSTEPS - 1) ? out : ((i & 1) ? bufB : bufA);
        node_step<<<grid, block, SMEM_BYTES>>>(src, W, b, gamma, dst);
    }
}

// round 17
// speedup vs baseline: 1.0302x; 1.0133x over previous
#include <cuda_runtime.h>
#include <cstdint>

// nODE: 50 Euler steps x <- x + DT*(x*gamma + tanh(x @ W^T + b)), M=32768, N=K=512.
// Legacy mma.sync.m16n8k8.tf32 (tcgen05 unavailable: harness PTX target = compute_103).
// R17 = R10/R16 champion (CTA 128x128, 8 warps 64x32, BK=32, 160B padded rows,
// k-permuted LDS.64 fragments, cp.async double buffer, hoisted addressing,
// warp-staggered chunks, bias-folded acc, tanh.approx) + epilogue Xin loads
// BATCHED per mt-block (MLP 2 -> 8) to shrink the exposed-latency tail.

constexpr int Mtot = 32768;
constexpr int Ntot = 512;
constexpr int Ktot = 512;
constexpr int BM = 128;
constexpr int BN = 128;
constexpr int BK = 32;
constexpr int NKT = Ktot / BK;          // 16
constexpr int ROWW = 40;                // words per smem row: 32 data + 8 pad (160B)
constexpr int A_WORDS = BM * ROWW;      // 5120
constexpr int B_WORDS = BN * ROWW;      // 5120
constexpr int STAGE_WORDS = A_WORDS + B_WORDS;       // 10240 (40 KB)
constexpr int SMEM_BYTES = 2 * STAGE_WORDS * 4;      // 81920
constexpr int NSTEPS = 50;
constexpr float DTF = 1.0f / 50.0f;

// ping-pong scratch (allocation-free rule: __device__ globals)
__device__ float g_bufA[(size_t)Mtot * Ntot];
__device__ float g_bufB[(size_t)Mtot * Ntot];

__device__ __forceinline__ void cp_async16(uint32_t dst, const void* src) {
    asm volatile("cp.async.cg.shared.global [%0], [%1], 16;" :: "r"(dst), "l"(src) : "memory");
}
__device__ __forceinline__ uint32_t smem_u32(const void* p) {
    uint32_t a;
    asm("{ .reg .u64 t; cvta.to.shared.u64 t, %1; cvt.u32.u64 %0, t; }" : "=r"(a) : "l"(p));
    return a;
}
// single-instruction MUFU.TANH (~5e-4 abs err; DT-scaled contribution ~2e-4 total)
__device__ __forceinline__ float tanh_approx(float z) {
    float r;
    asm("tanh.approx.f32 %0, %1;" : "=f"(r) : "f"(z));
    return r;
}

__global__ __launch_bounds__(256, 2)
void node_step(const float* __restrict__ Xin, const float* __restrict__ W,
               const float* __restrict__ bias, const float* __restrict__ gamma,
               float* __restrict__ Xout)
{
    extern __shared__ __align__(16) float smem[];
    const uint32_t sbase = smem_u32(smem);

    const int tid  = threadIdx.x;
    const int wid  = tid >> 5;
    const int lane = tid & 31;
    const int g    = lane >> 2;          // 0..7 (fragment row group)
    const int tg   = lane & 3;           // 0..3 (fragment k group)
    const int wm   = wid >> 2;           // 0..1: warp row -> 64 M rows each
    const int wn   = wid & 3;            // 0..3: warp col -> 32 N cols each
    const int m0   = blockIdx.y * BM;
    const int n0   = blockIdx.x * BN;

    // Epilogue constants hoisted; bias folded into accumulator init (exact same math).
    float2 bv[4], gv[4];
    #pragma unroll
    for (int nt = 0; nt < 4; nt++) {
        int n = n0 + wn * 32 + nt * 8 + 2 * tg;
        bv[nt] = *reinterpret_cast<const float2*>(bias + n);
        gv[nt] = *reinterpret_cast<const float2*>(gamma + n);
    }

    float acc[4][4][4];
    #pragma unroll
    for (int mt = 0; mt < 4; mt++)
        #pragma unroll
        for (int nt = 0; nt < 4; nt++) {
            acc[mt][nt][0] = bv[nt].x;   // (row g,   col 2tg)
            acc[mt][nt][1] = bv[nt].y;   // (row g,   col 2tg+1)
            acc[mt][nt][2] = bv[nt].x;   // (row g+8, col 2tg)
            acc[mt][nt][3] = bv[nt].y;   // (row g+8, col 2tg+1)
        }

    // ---- hoisted loader state: 256 thr, 16B each -> 32 rows/pass, 4 passes per tile ----
    const int lr = tid >> 3;             // 0..31 row within pass
    const int lc = tid & 7;              // 0..7 16B chunk within 128B row
    const uint32_t s_off = (uint32_t)(lr * ROWW + lc * 4) * 4;
    const float* gAk = Xin + (size_t)(m0 + lr) * Ktot + lc * 4;  // bumped +BK per issue
    const float* gBk = W   + (size_t)(n0 + lr) * Ktot + lc * 4;

    auto issue_loads = [&](int s) {
        const uint32_t a_s = sbase + (uint32_t)(s * STAGE_WORDS) * 4 + s_off;
        const uint32_t b_s = a_s + (uint32_t)A_WORDS * 4;
        #pragma unroll
        for (int i = 0; i < 4; i++)      // A: 128 rows in 4 passes of 32
            cp_async16(a_s + (uint32_t)(i * 32 * ROWW) * 4, gAk + (size_t)(i * 32) * Ktot);
        #pragma unroll
        for (int i = 0; i < 4; i++)      // B: 128 rows
            cp_async16(b_s + (uint32_t)(i * 32 * ROWW) * 4, gBk + (size_t)(i * 32) * Ktot);
        asm volatile("cp.async.commit_group;" ::: "memory");
        gAk += BK;
        gBk += BK;
    };

    issue_loads(0);

    const int cp0 = wid & 3;             // per-warp chunk phase (chunks commute)

    for (int kt = 0; kt < NKT; kt++) {
        const int s = kt & 1;
        // issue into s^1 is safe: end-of-previous-iteration barrier guarantees all
        // warps finished reading stage s^1 (compute of iter kt-1).
        if (kt + 1 < NKT) {
            issue_loads(s ^ 1);
            asm volatile("cp.async.wait_group 1;" ::: "memory");  // own stage-s group done
        } else {
            asm volatile("cp.async.wait_group 0;" ::: "memory");
        }
        __syncthreads();   // ALL threads' stage-s cp.asyncs complete -> data visible

        const float* As = smem + s * STAGE_WORDS;
        const float* Bs = As + A_WORDS;
        const float* a_base = As + (wm * 64 + g) * ROWW + 2 * tg;
        const float* b_base = Bs + (wn * 32 + g) * ROWW + 2 * tg;

        #pragma unroll
        for (int ch = 0; ch < 4; ch++) {             // k chunks of 8, warp-staggered
            const int chp = (ch + cp0) & 3;
            // k-permutation: MMA k-slot tg <- orig col 2tg, slot tg+4 <- 2tg+1.
            // Valid because A and B use the same permutation of the k axis.
            uint32_t af[4][4];
            #pragma unroll
            for (int mt = 0; mt < 4; mt++) {
                const float* p = a_base + mt * 16 * ROWW + chp * 8;
                float2 p1 = *reinterpret_cast<const float2*>(p);
                float2 p2 = *reinterpret_cast<const float2*>(p + 8 * ROWW);
                af[mt][0] = __float_as_uint(p1.x);   // (g,    k=tg)
                af[mt][1] = __float_as_uint(p2.x);   // (g+8,  k=tg)
                af[mt][2] = __float_as_uint(p1.y);   // (g,    k=tg+4)
                af[mt][3] = __float_as_uint(p2.y);   // (g+8,  k=tg+4)
            }
            uint32_t bf[4][2];
            #pragma unroll
            for (int nt = 0; nt < 4; nt++) {
                float2 q = *reinterpret_cast<const float2*>(b_base + nt * 8 * ROWW + chp * 8);
                bf[nt][0] = __float_as_uint(q.x);
                bf[nt][1] = __float_as_uint(q.y);
            }
            #pragma unroll
            for (int mt = 0; mt < 4; mt++)
                #pragma unroll
                for (int nt = 0; nt < 4; nt++)
                    asm volatile(
                        "mma.sync.aligned.m16n8k8.row.col.f32.tf32.tf32.f32 "
                        "{%0,%1,%2,%3}, {%4,%5,%6,%7}, {%8,%9}, {%0,%1,%2,%3};"
                        : "+f"(acc[mt][nt][0]), "+f"(acc[mt][nt][1]),
                          "+f"(acc[mt][nt][2]), "+f"(acc[mt][nt][3])
                        : "r"(af[mt][0]), "r"(af[mt][1]),
                          "r"(af[mt][2]), "r"(af[mt][3]),
                          "r"(bf[nt][0]), "r"(bf[nt][1]));
        }
        __syncthreads();   // protect stage s overwrite at iter kt+1
    }

    // ---- fused epilogue: out = x + DT*(x*gamma + tanh(C)) (bias already in C) ----
    // Per mt-block: batch ALL 8 Xin float2 loads first (MLP 8), then compute+store.
    // D frag: d0,d1 at (row g, cols 2tg,2tg+1); d2,d3 at (row g+8, same cols)
    #pragma unroll
    for (int mt = 0; mt < 4; mt++) {
        const float* xrow0 = Xin  + (size_t)(m0 + wm * 64 + mt * 16 + g) * Ntot;
        float*       orow0 = Xout + (size_t)(m0 + wm * 64 + mt * 16 + g) * Ntot;

        float2 xv[2][4];
        #pragma unroll
        for (int h = 0; h < 2; h++)
            #pragma unroll
            for (int nt = 0; nt < 4; nt++) {
                int n = n0 + wn * 32 + nt * 8 + 2 * tg;
                xv[h][nt] = *reinterpret_cast<const float2*>(xrow0 + (size_t)(h * 8) * Ntot + n);
            }

        #pragma unroll
        for (int h = 0; h < 2; h++) {
            float* orow = orow0 + (size_t)(h * 8) * Ntot;
            #pragma unroll
            for (int nt = 0; nt < 4; nt++) {
                int n = n0 + wn * 32 + nt * 8 + 2 * tg;
                float t0 = tanh_approx(acc[mt][nt][h * 2 + 0]);
                float t1 = tanh_approx(acc[mt][nt][h * 2 + 1]);
                float2 ov;
                ov.x = fmaf(DTF, fmaf(xv[h][nt].x, gv[nt].x, t0), xv[h][nt].x);
                ov.y = fmaf(DTF, fmaf(xv[h][nt].y, gv[nt].y, t1), xv[h][nt].y);
                *reinterpret_cast<float2*>(orow + n) = ov;
            }
        }
    }
}

extern "C" void kernel_launch(void* const* d_in, const int* in_sizes, int n_in,
                              void* d_out, int out_size)
{
    const float* x     = (const float*)d_in[0];
    const float* W     = (const float*)d_in[1];
    const float* b     = (const float*)d_in[2];
    const float* gamma = (const float*)d_in[3];
    float* out = (float*)d_out;

    float* bufA = nullptr;
    float* bufB = nullptr;
    cudaGetSymbolAddress((void**)&bufA, g_bufA);
    cudaGetSymbolAddress((void**)&bufB, g_bufB);

    cudaFuncSetAttribute(node_step, cudaFuncAttributeMaxDynamicSharedMemorySize, SMEM_BYTES);

    dim3 grid(Ntot / BN, Mtot / BM);   // (4, 256)
    dim3 block(256);

    for (int i = 0; i < NSTEPS; i++) {
        const float* src = (i == 0) ? x : ((i & 1) ? bufA : bufB);
        float* dst = (i == NSTEPS - 1) ? out : ((i & 1) ? bufB : bufA);
        node_step<<<grid, block, SMEM_BYTES>>>(src, W, b, gamma, dst);
    }
}